// round 5
// baseline (speedup 1.0000x reference)
#include <cuda_runtime.h>
#include <math.h>

#define HID   2048
#define NH    16
#define NKV   4
#define HD    128
#define SEQ   2048
#define BATCH 2
#define TOKENS (BATCH*SEQ)

// ---------------- scratch (no allocation allowed) ----------------
__device__ float g_Q[(size_t)TOKENS * NH  * HD];   // 33.5 MB
__device__ float g_K[(size_t)TOKENS * NKV * HD];   //  8.4 MB
__device__ float g_V[(size_t)TOKENS * NKV * HD];   //  8.4 MB
__device__ float g_O[(size_t)TOKENS * NH  * HD];   // 33.5 MB

// ---------------- SGEMM: C[M,N] = A[M,K] @ B[K,N], row-major, fp32 ----------------
#define BM 128
#define BN 128
#define BK 16
#define TM 8
#define TN 8

__global__ __launch_bounds__(256)
void sgemm_kernel(const float* __restrict__ A, const float* __restrict__ B,
                  float* __restrict__ C, int M, int N, int K) {
    __shared__ float As[BK][BM + 4];   // stride 132: kills store/read bank conflicts
    __shared__ float Bs[BK][BN];

    const int bx = blockIdx.x, by = blockIdx.y;
    const int tid = threadIdx.x;
    const int tx = tid & 15, ty = tid >> 4;

    const float* Ab = A + (size_t)by * BM * K;
    const float* Bb = B + (size_t)bx * BN;

    float acc[TM][TN];
#pragma unroll
    for (int i = 0; i < TM; i++)
#pragma unroll
        for (int j = 0; j < TN; j++) acc[i][j] = 0.f;

    for (int k0 = 0; k0 < K; k0 += BK) {
#pragma unroll
        for (int t = 0; t < 2; t++) {
            int id = tid + t * 256;
            // A tile: 128 rows x 4 float4-cols
            int ar = id >> 2, ac = (id & 3) * 4;
            float4 a = *(const float4*)(Ab + (size_t)ar * K + k0 + ac);
            As[ac + 0][ar] = a.x; As[ac + 1][ar] = a.y;
            As[ac + 2][ar] = a.z; As[ac + 3][ar] = a.w;
            // B tile: 16 rows x 32 float4-cols
            int br = id >> 5, bc = (id & 31) * 4;
            *(float4*)&Bs[br][bc] = *(const float4*)(Bb + (size_t)(k0 + br) * N + bc);
        }
        __syncthreads();

#pragma unroll
        for (int k = 0; k < BK; k++) {
            float ra[TM], rb[TN];
            *(float4*)&ra[0] = *(const float4*)&As[k][ty * TM];
            *(float4*)&ra[4] = *(const float4*)&As[k][ty * TM + 4];
            *(float4*)&rb[0] = *(const float4*)&Bs[k][tx * TN];
            *(float4*)&rb[4] = *(const float4*)&Bs[k][tx * TN + 4];
#pragma unroll
            for (int i = 0; i < TM; i++)
#pragma unroll
                for (int j = 0; j < TN; j++)
                    acc[i][j] = fmaf(ra[i], rb[j], acc[i][j]);
        }
        __syncthreads();
    }

    float* Cb = C + (size_t)(by * BM + ty * TM) * N + bx * BN + tx * TN;
#pragma unroll
    for (int i = 0; i < TM; i++) {
        *(float4*)(Cb + (size_t)i * N)     = make_float4(acc[i][0], acc[i][1], acc[i][2], acc[i][3]);
        *(float4*)(Cb + (size_t)i * N + 4) = make_float4(acc[i][4], acc[i][5], acc[i][6], acc[i][7]);
    }
}

// ---------------- fused RMSNorm (per head, eps 1e-6) + RoPE, in place ----------------
__global__ void rmsnorm_rope_kernel(float* __restrict__ X, const float* __restrict__ w,
                                    const float* __restrict__ cs, const float* __restrict__ sn,
                                    int nheads) {
    const int tok = blockIdx.x;       // b*SEQ + s
    const int h   = blockIdx.y;
    const int d   = threadIdx.x;      // 0..127
    const int s   = tok & (SEQ - 1);

    float* row = X + (size_t)tok * nheads * HD + h * HD;
    float x = row[d];

    float ss = x * x;
#pragma unroll
    for (int o = 16; o > 0; o >>= 1) ss += __shfl_xor_sync(0xffffffffu, ss, o);

    __shared__ float wsum[4];
    __shared__ float sv[HD];
    if ((d & 31) == 0) wsum[d >> 5] = ss;
    __syncthreads();
    float tot = wsum[0] + wsum[1] + wsum[2] + wsum[3];
    float r = rsqrtf(tot * (1.0f / HD) + 1e-6f);
    float v = x * r * w[d];
    sv[d] = v;
    __syncthreads();
    float rot = (d < 64) ? -sv[d + 64] : sv[d - 64];
    row[d] = v * cs[(size_t)s * HD + d] + rot * sn[(size_t)s * HD + d];
}

// ---------------- causal flash attention, fp32, GQA (kvh = h>>2) ----------------
#define FBM 64
#define FBN 64
#define QLD 132   // padded row stride for Qs/Ks/Vs (conflict-free)
#define SLD 68    // padded row stride for P tile

#define FLASH_SMEM_FLOATS (3 * FBM * QLD + FBM * SLD)
#define FLASH_SMEM_BYTES  (FLASH_SMEM_FLOATS * 4)

__global__ __launch_bounds__(256)
void flash_kernel(const float* __restrict__ Q, const float* __restrict__ K,
                  const float* __restrict__ V, float* __restrict__ O) {
    extern __shared__ float sm[];
    float* Qs = sm;                     // [64][132]
    float* Ks = Qs + FBM * QLD;         // [64][132]
    float* Vs = Ks + FBM * QLD;         // [64][132]
    float* Ss = Vs + FBM * QLD;         // [64][68]

    const int qt = blockIdx.x;          // q tile 0..31
    const int h  = blockIdx.y;
    const int b  = blockIdx.z;
    const int kvh = h >> 2;             // n_rep = 4
    const int tid = threadIdx.x;
    const int tx = tid & 15, ty = tid >> 4;
    const float scale = 0.08838834764831845f;  // 1/sqrt(128)

    const float* Qg = Q + ((size_t)(b * SEQ + qt * FBM)) * (NH  * HD) + h   * HD;
    const float* Kg = K + ((size_t)(b * SEQ))            * (NKV * HD) + kvh * HD;
    const float* Vg = V + ((size_t)(b * SEQ))            * (NKV * HD) + kvh * HD;

    // load Q tile 64x128
#pragma unroll
    for (int t = 0; t < 8; t++) {
        int id = tid + t * 256;
        int r = id >> 5, c = (id & 31) * 4;
        *(float4*)&Qs[r * QLD + c] = *(const float4*)(Qg + (size_t)r * (NH * HD) + c);
    }

    float m[4], l[4], acc[4][8];
#pragma unroll
    for (int i = 0; i < 4; i++) {
        m[i] = -1e30f; l[i] = 0.f;
#pragma unroll
        for (int d8 = 0; d8 < 8; d8++) acc[i][d8] = 0.f;
    }

    for (int jt = 0; jt <= qt; jt++) {
        __syncthreads();   // prev-iter Ks/Vs/Ss reads complete
#pragma unroll
        for (int t = 0; t < 8; t++) {
            int id = tid + t * 256;
            int r = id >> 5, c = (id & 31) * 4;
            *(float4*)&Ks[r * QLD + c] = *(const float4*)(Kg + (size_t)(jt * FBN + r) * (NKV * HD) + c);
            *(float4*)&Vs[r * QLD + c] = *(const float4*)(Vg + (size_t)(jt * FBN + r) * (NKV * HD) + c);
        }
        __syncthreads();

        // S = Q @ K^T  — rows ty+16i, cols tx+16j (interleaved: conflict-free LDS.128)
        float s[4][4];
#pragma unroll
        for (int i = 0; i < 4; i++)
#pragma unroll
            for (int j = 0; j < 4; j++) s[i][j] = 0.f;

        for (int k = 0; k < HD; k += 4) {
            float4 qa[4], kb[4];
#pragma unroll
            for (int i = 0; i < 4; i++) qa[i] = *(const float4*)&Qs[(ty + 16 * i) * QLD + k];
#pragma unroll
            for (int j = 0; j < 4; j++) kb[j] = *(const float4*)&Ks[(tx + 16 * j) * QLD + k];
#pragma unroll
            for (int i = 0; i < 4; i++)
#pragma unroll
                for (int j = 0; j < 4; j++)
                    s[i][j] += qa[i].x * kb[j].x + qa[i].y * kb[j].y
                             + qa[i].z * kb[j].z + qa[i].w * kb[j].w;
        }

        const bool diag = (jt == qt);
#pragma unroll
        for (int i = 0; i < 4; i++) {
            int rg = qt * FBM + ty + 16 * i;
#pragma unroll
            for (int j = 0; j < 4; j++) {
                float val = s[i][j] * scale;
                if (diag && (jt * FBN + tx + 16 * j) > rg) val = -1e30f;
                s[i][j] = val;
            }
        }

        // online softmax per row (reduce over the 16 tx lanes)
#pragma unroll
        for (int i = 0; i < 4; i++) {
            float mx = fmaxf(fmaxf(s[i][0], s[i][1]), fmaxf(s[i][2], s[i][3]));
#pragma unroll
            for (int o = 8; o > 0; o >>= 1) mx = fmaxf(mx, __shfl_xor_sync(0xffffffffu, mx, o));
            float mn = fmaxf(m[i], mx);
            float alpha = __expf(m[i] - mn);
            m[i] = mn;
            float ls = 0.f;
#pragma unroll
            for (int j = 0; j < 4; j++) {
                float p = __expf(s[i][j] - mn);
                Ss[(ty + 16 * i) * SLD + tx + 16 * j] = p;
                ls += p;
            }
#pragma unroll
            for (int o = 8; o > 0; o >>= 1) ls += __shfl_xor_sync(0xffffffffu, ls, o);
            l[i] = l[i] * alpha + ls;
#pragma unroll
            for (int d8 = 0; d8 < 8; d8++) acc[i][d8] *= alpha;
        }
        __syncthreads();   // Ss ready

        // O += P @ V  — thread owns d = tx*4+0..3 and 64+tx*4+0..3
#pragma unroll 4
        for (int c = 0; c < FBN; c++) {
            float4 v0 = *(const float4*)&Vs[c * QLD + tx * 4];
            float4 v1 = *(const float4*)&Vs[c * QLD + 64 + tx * 4];
#pragma unroll
            for (int i = 0; i < 4; i++) {
                float p = Ss[(ty + 16 * i) * SLD + c];
                acc[i][0] = fmaf(p, v0.x, acc[i][0]);
                acc[i][1] = fmaf(p, v0.y, acc[i][1]);
                acc[i][2] = fmaf(p, v0.z, acc[i][2]);
                acc[i][3] = fmaf(p, v0.w, acc[i][3]);
                acc[i][4] = fmaf(p, v1.x, acc[i][4]);
                acc[i][5] = fmaf(p, v1.y, acc[i][5]);
                acc[i][6] = fmaf(p, v1.z, acc[i][6]);
                acc[i][7] = fmaf(p, v1.w, acc[i][7]);
            }
        }
    }

    // normalize + store: O[token][h*128 + d]
#pragma unroll
    for (int i = 0; i < 4; i++) {
        float inv = 1.0f / l[i];
        float* Og = O + ((size_t)(b * SEQ + qt * FBM + ty + 16 * i)) * (NH * HD) + h * HD;
        float4 o0 = make_float4(acc[i][0] * inv, acc[i][1] * inv, acc[i][2] * inv, acc[i][3] * inv);
        float4 o1 = make_float4(acc[i][4] * inv, acc[i][5] * inv, acc[i][6] * inv, acc[i][7] * inv);
        *(float4*)(Og + tx * 4)      = o0;
        *(float4*)(Og + 64 + tx * 4) = o1;
    }
}

// ---------------- launch ----------------
extern "C" void kernel_launch(void* const* d_in, const int* in_sizes, int n_in,
                              void* d_out, int out_size) {
    const float* X  = (const float*)d_in[0];
    const float* cs = (const float*)d_in[1];
    const float* sn = (const float*)d_in[2];
    const float* Wq = (const float*)d_in[3];
    const float* Wk = (const float*)d_in[4];
    const float* Wv = (const float*)d_in[5];
    const float* Wo = (const float*)d_in[6];
    const float* qw = (const float*)d_in[7];
    const float* kw = (const float*)d_in[8];
    float* out = (float*)d_out;

    float *Q, *K, *V, *O;
    cudaGetSymbolAddress((void**)&Q, g_Q);
    cudaGetSymbolAddress((void**)&K, g_K);
    cudaGetSymbolAddress((void**)&V, g_V);
    cudaGetSymbolAddress((void**)&O, g_O);

    cudaFuncSetAttribute(flash_kernel, cudaFuncAttributeMaxDynamicSharedMemorySize,
                         FLASH_SMEM_BYTES);

    // QKV projections
    sgemm_kernel<<<dim3(2048 / BN, TOKENS / BM), 256>>>(X, Wq, Q, TOKENS, 2048, HID);
    sgemm_kernel<<<dim3( 512 / BN, TOKENS / BM), 256>>>(X, Wk, K, TOKENS,  512, HID);
    sgemm_kernel<<<dim3( 512 / BN, TOKENS / BM), 256>>>(X, Wv, V, TOKENS,  512, HID);

    // per-head RMSNorm + RoPE (in place)
    rmsnorm_rope_kernel<<<dim3(TOKENS, NH),  HD>>>(Q, qw, cs, sn, NH);
    rmsnorm_rope_kernel<<<dim3(TOKENS, NKV), HD>>>(K, kw, cs, sn, NKV);

    // causal GQA attention
    flash_kernel<<<dim3(SEQ / FBM, NH, BATCH), 256, FLASH_SMEM_BYTES>>>(Q, K, V, O);

    // output projection
    sgemm_kernel<<<dim3(2048 / BN, TOKENS / BM), 256>>>(O, Wo, out, TOKENS, 2048, HID);
}

// round 9
// speedup vs baseline: 1.1914x; 1.1914x over previous
#include <cuda_runtime.h>
#include <math.h>
#include <stdint.h>

#define HID   2048
#define NH    16
#define NKV   4
#define HD    128
#define SEQ   2048
#define BATCH 2
#define TOKENS (BATCH*SEQ)

// ---------------- scratch (no allocation allowed) ----------------
__device__ float g_Q[(size_t)TOKENS * NH  * HD];
__device__ float g_K[(size_t)TOKENS * NKV * HD];
__device__ float g_V[(size_t)TOKENS * NKV * HD];
__device__ float g_O[(size_t)TOKENS * NH  * HD];
__device__ float g_WqT[(size_t)2048 * 2048];
__device__ float g_WkT[(size_t)512  * 2048];
__device__ float g_WvT[(size_t)512  * 2048];
__device__ float g_WoT[(size_t)2048 * 2048];

// ---------------- PTX helpers ----------------
__device__ __forceinline__ uint32_t smem_u32(const void* p) {
    uint32_t a;
    asm("{ .reg .u64 t; cvta.to.shared.u64 t, %1; cvt.u32.u64 %0, t; }" : "=r"(a) : "l"(p));
    return a;
}

#define CP_ASYNC16(dst, src) \
    asm volatile("cp.async.cg.shared.global [%0], [%1], 16;" :: "r"(dst), "l"(src))
#define CP_COMMIT() asm volatile("cp.async.commit_group;" ::: "memory")
#define CP_WAIT(n)  asm volatile("cp.async.wait_group %0;" :: "n"(n) : "memory")

__device__ __forceinline__ void ldsm_x4(uint32_t addr, uint32_t r[4]) {
    asm volatile("ldmatrix.sync.aligned.m8n8.x4.shared.b16 {%0,%1,%2,%3}, [%4];"
                 : "=r"(r[0]), "=r"(r[1]), "=r"(r[2]), "=r"(r[3]) : "r"(addr));
}
__device__ __forceinline__ void ldsm_x2(uint32_t addr, uint32_t r[2]) {
    asm volatile("ldmatrix.sync.aligned.m8n8.x2.shared.b16 {%0,%1}, [%2];"
                 : "=r"(r[0]), "=r"(r[1]) : "r"(addr));
}
__device__ __forceinline__ void mma_tf32(float c[4], const uint32_t a[4], const uint32_t b[2]) {
    asm volatile(
        "mma.sync.aligned.m16n8k8.row.col.f32.tf32.tf32.f32 "
        "{%0,%1,%2,%3}, {%4,%5,%6,%7}, {%8,%9}, {%0,%1,%2,%3};"
        : "+f"(c[0]), "+f"(c[1]), "+f"(c[2]), "+f"(c[3])
        : "r"(a[0]), "r"(a[1]), "r"(a[2]), "r"(a[3]), "r"(b[0]), "r"(b[1]));
}

// error-free tf32 split: x = hi + lo (hi,lo round-to-nearest tf32)
__device__ __forceinline__ void tf32_split(uint32_t raw, uint32_t& hi, uint32_t& lo) {
    float x = __uint_as_float(raw);
    uint32_t h;
    asm("cvt.rna.tf32.f32 %0, %1;" : "=r"(h) : "f"(x));
    float r = x - __uint_as_float(h);
    uint32_t lw;
    asm("cvt.rna.tf32.f32 %0, %1;" : "=r"(lw) : "f"(r));
    hi = h; lo = lw;
}

// ---------------- weight transpose: Wt[n][k] = W[k][n] ----------------
__global__ void transpose_kernel(const float* __restrict__ W, float* __restrict__ Wt,
                                 int K, int N) {
    __shared__ float t[32][33];
    int x = blockIdx.x * 32 + threadIdx.x;   // n
    int y0 = blockIdx.y * 32;                // k base
#pragma unroll
    for (int i = threadIdx.y; i < 32; i += 8)
        t[i][threadIdx.x] = W[(size_t)(y0 + i) * N + x];
    __syncthreads();
    int xo = y0 + threadIdx.x;               // k
    int yo0 = blockIdx.x * 32;               // n base
#pragma unroll
    for (int i = threadIdx.y; i < 32; i += 8)
        Wt[(size_t)(yo0 + i) * K + xo] = t[threadIdx.x][i];
}

// ---------------- tf32x3 mma.sync GEMM: C[M,N] = A[M,K] @ Bt[N,K]^T ----------------
// A row-major (K contig), Bt row-major (K contig). 128x128 CTA tile, BK=32,
// 8 warps each computing 64x32 via 4x4 m16n8k8 fragments, 3-term tf32
// compensation (near-fp32 accuracy). 2-stage cp.async.
#define GLD 36                                 /* padded floats per smem row */
#define GSTAGE_FLOATS (128 * GLD)              /* one matrix, one stage */
#define GSTAGE_BYTES (2 * GSTAGE_FLOATS * 4)   /* A + B */
#define GM_SMEM_BYTES (2 * GSTAGE_BYTES)       /* 2 stages = 73728 B */

__global__ __launch_bounds__(256, 2)
void tf32_gemm_kernel(const float* __restrict__ A, const float* __restrict__ Bt,
                      float* __restrict__ C, int M, int N, int K) {
    extern __shared__ float gsm[];
    const uint32_t sbase = smem_u32(gsm);

    const int tid = threadIdx.x;
    const int wid = tid >> 5, l = tid & 31;
    const int wm = wid >> 2;        // 0..1  -> M offset wm*64
    const int wn = wid & 3;         // 0..3  -> N offset wn*32
    const int bn = blockIdx.x, bm = blockIdx.y;

    const float* Ab = A  + (size_t)bm * 128 * K;
    const float* Bb = Bt + (size_t)bn * 128 * K;
    const int KT = K >> 5;

    const int a_row = l & 15, a_cg = (l >> 4);
    const int b_row = l & 7,  b_cg = (l >> 3) & 1;

    float acc[4][4][4];
#pragma unroll
    for (int mt = 0; mt < 4; mt++)
#pragma unroll
        for (int nt = 0; nt < 4; nt++)
#pragma unroll
            for (int r = 0; r < 4; r++) acc[mt][nt][r] = 0.f;

    auto load_stage = [&](int s, int kt) {
        uint32_t ab = sbase + s * GSTAGE_BYTES;
        uint32_t bb = ab + GSTAGE_FLOATS * 4;
        int k0 = kt << 5;
#pragma unroll
        for (int i = 0; i < 4; i++) {
            int c = tid + i * 256;
            int row = c >> 3, ch = c & 7;
            uint32_t off = (uint32_t)(row * GLD + ch * 4) * 4;
            CP_ASYNC16(ab + off, Ab + (size_t)row * K + k0 + ch * 4);
            CP_ASYNC16(bb + off, Bb + (size_t)row * K + k0 + ch * 4);
        }
    };

    load_stage(0, 0);
    CP_COMMIT();

    for (int kt = 0; kt < KT; kt++) {
        const int s = kt & 1;
        CP_WAIT(0);
        __syncthreads();
        if (kt + 1 < KT) { load_stage(s ^ 1, kt + 1); CP_COMMIT(); }

        const uint32_t ab = sbase + s * GSTAGE_BYTES;
        const uint32_t bb = ab + GSTAGE_FLOATS * 4;

#pragma unroll
        for (int kk = 0; kk < 4; kk++) { // 4 x K=8
            const int k0 = kk * 8;

            // B fragments: split once per kk
            uint32_t bhi[4][2], blo[4][2];
#pragma unroll
            for (int nt = 0; nt < 4; nt++) {
                uint32_t braw[2];
                ldsm_x2(bb + (uint32_t)((wn * 32 + nt * 8 + b_row) * GLD
                                        + k0 + b_cg * 4) * 4, braw);
                tf32_split(braw[0], bhi[nt][0], blo[nt][0]);
                tf32_split(braw[1], bhi[nt][1], blo[nt][1]);
            }

            // A fragments: split per mt, then 3-term MMA
#pragma unroll
            for (int mt = 0; mt < 4; mt++) {
                uint32_t araw[4], ahi[4], alo[4];
                ldsm_x4(ab + (uint32_t)((wm * 64 + mt * 16 + a_row) * GLD
                                        + k0 + a_cg * 4) * 4, araw);
#pragma unroll
                for (int r = 0; r < 4; r++) tf32_split(araw[r], ahi[r], alo[r]);
#pragma unroll
                for (int nt = 0; nt < 4; nt++) {
                    mma_tf32(acc[mt][nt], alo, bhi[nt]);   // A_lo * B_hi
                    mma_tf32(acc[mt][nt], ahi, blo[nt]);   // A_hi * B_lo
                    mma_tf32(acc[mt][nt], ahi, bhi[nt]);   // A_hi * B_hi
                }
            }
        }
        __syncthreads();
    }

    const int er = l >> 2, ec = (l & 3) * 2;
#pragma unroll
    for (int mt = 0; mt < 4; mt++) {
        int row = bm * 128 + wm * 64 + mt * 16 + er;
#pragma unroll
        for (int nt = 0; nt < 4; nt++) {
            int col = bn * 128 + wn * 32 + nt * 8 + ec;
            *(float2*)(C + (size_t)row * N + col) =
                make_float2(acc[mt][nt][0], acc[mt][nt][1]);
            *(float2*)(C + (size_t)(row + 8) * N + col) =
                make_float2(acc[mt][nt][2], acc[mt][nt][3]);
        }
    }
}

// ---------------- fused RMSNorm (per head, eps 1e-6) + RoPE, in place ----------------
__global__ void rmsnorm_rope_kernel(float* __restrict__ X, const float* __restrict__ w,
                                    const float* __restrict__ cs, const float* __restrict__ sn,
                                    int nheads) {
    const int tok = blockIdx.x;
    const int h   = blockIdx.y;
    const int d   = threadIdx.x;
    const int s   = tok & (SEQ - 1);

    float* row = X + (size_t)tok * nheads * HD + h * HD;
    float x = row[d];

    float ss = x * x;
#pragma unroll
    for (int o = 16; o > 0; o >>= 1) ss += __shfl_xor_sync(0xffffffffu, ss, o);

    __shared__ float wsum[4];
    __shared__ float sv[HD];
    if ((d & 31) == 0) wsum[d >> 5] = ss;
    __syncthreads();
    float tot = wsum[0] + wsum[1] + wsum[2] + wsum[3];
    float r = rsqrtf(tot * (1.0f / HD) + 1e-6f);
    float v = x * r * w[d];
    sv[d] = v;
    __syncthreads();
    float rot = (d < 64) ? -sv[d + 64] : sv[d - 64];
    row[d] = v * cs[(size_t)s * HD + d] + rot * sn[(size_t)s * HD + d];
}

// ---------------- causal flash attention, fp32, GQA (kvh = h>>2) ----------------
#define FBM 64
#define FBN 64
#define QLD 132
#define SLD 68

#define FLASH_SMEM_FLOATS (3 * FBM * QLD + FBM * SLD)
#define FLASH_SMEM_BYTES  (FLASH_SMEM_FLOATS * 4)

__global__ __launch_bounds__(256)
void flash_kernel(const float* __restrict__ Q, const float* __restrict__ K,
                  const float* __restrict__ V, float* __restrict__ O) {
    extern __shared__ float sm[];
    float* Qs = sm;
    float* Ks = Qs + FBM * QLD;
    float* Vs = Ks + FBM * QLD;
    float* Ss = Vs + FBM * QLD;

    const int qt = blockIdx.x;
    const int h  = blockIdx.y;
    const int b  = blockIdx.z;
    const int kvh = h >> 2;
    const int tid = threadIdx.x;
    const int tx = tid & 15, ty = tid >> 4;
    const float scale = 0.08838834764831845f;

    const float* Qg = Q + ((size_t)(b * SEQ + qt * FBM)) * (NH  * HD) + h   * HD;
    const float* Kg = K + ((size_t)(b * SEQ))            * (NKV * HD) + kvh * HD;
    const float* Vg = V + ((size_t)(b * SEQ))            * (NKV * HD) + kvh * HD;

#pragma unroll
    for (int t = 0; t < 8; t++) {
        int id = tid + t * 256;
        int r = id >> 5, c = (id & 31) * 4;
        *(float4*)&Qs[r * QLD + c] = *(const float4*)(Qg + (size_t)r * (NH * HD) + c);
    }

    float m[4], l[4], acc[4][8];
#pragma unroll
    for (int i = 0; i < 4; i++) {
        m[i] = -1e30f; l[i] = 0.f;
#pragma unroll
        for (int d8 = 0; d8 < 8; d8++) acc[i][d8] = 0.f;
    }

    for (int jt = 0; jt <= qt; jt++) {
        __syncthreads();
#pragma unroll
        for (int t = 0; t < 8; t++) {
            int id = tid + t * 256;
            int r = id >> 5, c = (id & 31) * 4;
            *(float4*)&Ks[r * QLD + c] = *(const float4*)(Kg + (size_t)(jt * FBN + r) * (NKV * HD) + c);
            *(float4*)&Vs[r * QLD + c] = *(const float4*)(Vg + (size_t)(jt * FBN + r) * (NKV * HD) + c);
        }
        __syncthreads();

        float s[4][4];
#pragma unroll
        for (int i = 0; i < 4; i++)
#pragma unroll
            for (int j = 0; j < 4; j++) s[i][j] = 0.f;

        for (int k = 0; k < HD; k += 4) {
            float4 qa[4], kb[4];
#pragma unroll
            for (int i = 0; i < 4; i++) qa[i] = *(const float4*)&Qs[(ty + 16 * i) * QLD + k];
#pragma unroll
            for (int j = 0; j < 4; j++) kb[j] = *(const float4*)&Ks[(tx + 16 * j) * QLD + k];
#pragma unroll
            for (int i = 0; i < 4; i++)
#pragma unroll
                for (int j = 0; j < 4; j++)
                    s[i][j] += qa[i].x * kb[j].x + qa[i].y * kb[j].y
                             + qa[i].z * kb[j].z + qa[i].w * kb[j].w;
        }

        const bool diag = (jt == qt);
#pragma unroll
        for (int i = 0; i < 4; i++) {
            int rg = qt * FBM + ty + 16 * i;
#pragma unroll
            for (int j = 0; j < 4; j++) {
                float val = s[i][j] * scale;
                if (diag && (jt * FBN + tx + 16 * j) > rg) val = -1e30f;
                s[i][j] = val;
            }
        }

#pragma unroll
        for (int i = 0; i < 4; i++) {
            float mx = fmaxf(fmaxf(s[i][0], s[i][1]), fmaxf(s[i][2], s[i][3]));
#pragma unroll
            for (int o = 8; o > 0; o >>= 1) mx = fmaxf(mx, __shfl_xor_sync(0xffffffffu, mx, o));
            float mn = fmaxf(m[i], mx);
            float alpha = __expf(m[i] - mn);
            m[i] = mn;
            float ls = 0.f;
#pragma unroll
            for (int j = 0; j < 4; j++) {
                float p = __expf(s[i][j] - mn);
                Ss[(ty + 16 * i) * SLD + tx + 16 * j] = p;
                ls += p;
            }
#pragma unroll
            for (int o = 8; o > 0; o >>= 1) ls += __shfl_xor_sync(0xffffffffu, ls, o);
            l[i] = l[i] * alpha + ls;
#pragma unroll
            for (int d8 = 0; d8 < 8; d8++) acc[i][d8] *= alpha;
        }
        __syncthreads();

#pragma unroll 4
        for (int c = 0; c < FBN; c++) {
            float4 v0 = *(const float4*)&Vs[c * QLD + tx * 4];
            float4 v1 = *(const float4*)&Vs[c * QLD + 64 + tx * 4];
#pragma unroll
            for (int i = 0; i < 4; i++) {
                float p = Ss[(ty + 16 * i) * SLD + c];
                acc[i][0] = fmaf(p, v0.x, acc[i][0]);
                acc[i][1] = fmaf(p, v0.y, acc[i][1]);
                acc[i][2] = fmaf(p, v0.z, acc[i][2]);
                acc[i][3] = fmaf(p, v0.w, acc[i][3]);
                acc[i][4] = fmaf(p, v1.x, acc[i][4]);
                acc[i][5] = fmaf(p, v1.y, acc[i][5]);
                acc[i][6] = fmaf(p, v1.z, acc[i][6]);
                acc[i][7] = fmaf(p, v1.w, acc[i][7]);
            }
        }
    }

#pragma unroll
    for (int i = 0; i < 4; i++) {
        float inv = 1.0f / l[i];
        float* Og = O + ((size_t)(b * SEQ + qt * FBM + ty + 16 * i)) * (NH * HD) + h * HD;
        float4 o0 = make_float4(acc[i][0] * inv, acc[i][1] * inv, acc[i][2] * inv, acc[i][3] * inv);
        float4 o1 = make_float4(acc[i][4] * inv, acc[i][5] * inv, acc[i][6] * inv, acc[i][7] * inv);
        *(float4*)(Og + tx * 4)      = o0;
        *(float4*)(Og + 64 + tx * 4) = o1;
    }
}

// ---------------- launch ----------------
extern "C" void kernel_launch(void* const* d_in, const int* in_sizes, int n_in,
                              void* d_out, int out_size) {
    const float* X  = (const float*)d_in[0];
    const float* cs = (const float*)d_in[1];
    const float* sn = (const float*)d_in[2];
    const float* Wq = (const float*)d_in[3];
    const float* Wk = (const float*)d_in[4];
    const float* Wv = (const float*)d_in[5];
    const float* Wo = (const float*)d_in[6];
    const float* qw = (const float*)d_in[7];
    const float* kw = (const float*)d_in[8];
    float* out = (float*)d_out;

    float *Q, *K, *V, *O, *WqT, *WkT, *WvT, *WoT;
    cudaGetSymbolAddress((void**)&Q, g_Q);
    cudaGetSymbolAddress((void**)&K, g_K);
    cudaGetSymbolAddress((void**)&V, g_V);
    cudaGetSymbolAddress((void**)&O, g_O);
    cudaGetSymbolAddress((void**)&WqT, g_WqT);
    cudaGetSymbolAddress((void**)&WkT, g_WkT);
    cudaGetSymbolAddress((void**)&WvT, g_WvT);
    cudaGetSymbolAddress((void**)&WoT, g_WoT);

    cudaFuncSetAttribute(tf32_gemm_kernel, cudaFuncAttributeMaxDynamicSharedMemorySize,
                         GM_SMEM_BYTES);
    cudaFuncSetAttribute(flash_kernel, cudaFuncAttributeMaxDynamicSharedMemorySize,
                         FLASH_SMEM_BYTES);

    // weight transposes: Wt[n][k] = W[k][n]
    transpose_kernel<<<dim3(2048 / 32, 2048 / 32), dim3(32, 8)>>>(Wq, WqT, 2048, 2048);
    transpose_kernel<<<dim3( 512 / 32, 2048 / 32), dim3(32, 8)>>>(Wk, WkT, 2048,  512);
    transpose_kernel<<<dim3( 512 / 32, 2048 / 32), dim3(32, 8)>>>(Wv, WvT, 2048,  512);
    transpose_kernel<<<dim3(2048 / 32, 2048 / 32), dim3(32, 8)>>>(Wo, WoT, 2048, 2048);

    // QKV projections (tf32x3 mma.sync)
    tf32_gemm_kernel<<<dim3(2048 / 128, TOKENS / 128), 256, GM_SMEM_BYTES>>>(
        X, WqT, Q, TOKENS, 2048, HID);
    tf32_gemm_kernel<<<dim3( 512 / 128, TOKENS / 128), 256, GM_SMEM_BYTES>>>(
        X, WkT, K, TOKENS,  512, HID);
    tf32_gemm_kernel<<<dim3( 512 / 128, TOKENS / 128), 256, GM_SMEM_BYTES>>>(
        X, WvT, V, TOKENS,  512, HID);

    // per-head RMSNorm + RoPE (in place)
    rmsnorm_rope_kernel<<<dim3(TOKENS, NH),  HD>>>(Q, qw, cs, sn, NH);
    rmsnorm_rope_kernel<<<dim3(TOKENS, NKV), HD>>>(K, kw, cs, sn, NKV);

    // causal GQA attention (fp32 flash)
    flash_kernel<<<dim3(SEQ / FBM, NH, BATCH), 256, FLASH_SMEM_BYTES>>>(Q, K, V, O);

    // output projection (tf32x3 mma.sync)
    tf32_gemm_kernel<<<dim3(2048 / 128, TOKENS / 128), 256, GM_SMEM_BYTES>>>(
        O, WoT, out, TOKENS, 2048, HID);
}

// round 11
// speedup vs baseline: 2.5244x; 2.1188x over previous
#include <cuda_runtime.h>
#include <cuda_bf16.h>
#include <math.h>
#include <stdint.h>

typedef __nv_bfloat16 bf16;

#define HID   2048
#define NH    16
#define NKV   4
#define HD    128
#define SEQ   2048
#define BATCH 2
#define TOKENS (BATCH*SEQ)

// ---------------- scratch (no allocation allowed) ----------------
__device__ float g_Q[(size_t)TOKENS * NH  * HD];
__device__ float g_K[(size_t)TOKENS * NKV * HD];
__device__ float g_V[(size_t)TOKENS * NKV * HD];
__device__ bf16  g_Xh[(size_t)TOKENS * HID],        g_Xl[(size_t)TOKENS * HID];
__device__ bf16  g_Qh[(size_t)TOKENS * NH  * HD],   g_Ql[(size_t)TOKENS * NH  * HD];
__device__ bf16  g_Kh[(size_t)TOKENS * NKV * HD],   g_Kl[(size_t)TOKENS * NKV * HD];
__device__ bf16  g_Vth[(size_t)BATCH * NKV * HD * SEQ], g_Vtl[(size_t)BATCH * NKV * HD * SEQ];
__device__ bf16  g_Oh[(size_t)TOKENS * NH  * HD],   g_Ol[(size_t)TOKENS * NH  * HD];
__device__ bf16  g_WqTh[(size_t)2048 * 2048], g_WqTl[(size_t)2048 * 2048];
__device__ bf16  g_WkTh[(size_t)512  * 2048], g_WkTl[(size_t)512  * 2048];
__device__ bf16  g_WvTh[(size_t)512  * 2048], g_WvTl[(size_t)512  * 2048];
__device__ bf16  g_WoTh[(size_t)2048 * 2048], g_WoTl[(size_t)2048 * 2048];

// ---------------- helpers ----------------
__device__ __forceinline__ uint32_t smem_u32(const void* p) {
    uint32_t a;
    asm("{ .reg .u64 t; cvta.to.shared.u64 t, %1; cvt.u32.u64 %0, t; }" : "=r"(a) : "l"(p));
    return a;
}

#define CP_ASYNC16(dst, src) \
    asm volatile("cp.async.cg.shared.global [%0], [%1], 16;" :: "r"(dst), "l"(src))
#define CP_COMMIT() asm volatile("cp.async.commit_group;" ::: "memory")
#define CP_WAIT(n)  asm volatile("cp.async.wait_group %0;" :: "n"(n) : "memory")

__device__ __forceinline__ void ldsm_x4(uint32_t addr, uint32_t r[4]) {
    asm volatile("ldmatrix.sync.aligned.m8n8.x4.shared.b16 {%0,%1,%2,%3}, [%4];"
                 : "=r"(r[0]), "=r"(r[1]), "=r"(r[2]), "=r"(r[3]) : "r"(addr));
}
__device__ __forceinline__ void ldsm_x2(uint32_t addr, uint32_t r[2]) {
    asm volatile("ldmatrix.sync.aligned.m8n8.x2.shared.b16 {%0,%1}, [%2];"
                 : "=r"(r[0]), "=r"(r[1]) : "r"(addr));
}
__device__ __forceinline__ void mma_bf16(float c[4], const uint32_t a[4], const uint32_t b[2]) {
    asm volatile(
        "mma.sync.aligned.m16n8k16.row.col.f32.bf16.bf16.f32 "
        "{%0,%1,%2,%3}, {%4,%5,%6,%7}, {%8,%9}, {%0,%1,%2,%3};"
        : "+f"(c[0]), "+f"(c[1]), "+f"(c[2]), "+f"(c[3])
        : "r"(a[0]), "r"(a[1]), "r"(a[2]), "r"(a[3]), "r"(b[0]), "r"(b[1]));
}

__device__ __forceinline__ void fsplit2(float x, bf16& h, bf16& l) {
    h = __float2bfloat16(x);
    l = __float2bfloat16(x - __bfloat162float(h));
}

// ---------------- elementwise split: fp32 -> hi/lo planes ----------------
__global__ void split_kernel(const float* __restrict__ in,
                             bf16* __restrict__ hi, bf16* __restrict__ lo) {
    int i = (blockIdx.x * 256 + threadIdx.x) * 4;
    float4 v = *(const float4*)(in + i);
    bf16 h[4], l[4];
    fsplit2(v.x, h[0], l[0]); fsplit2(v.y, h[1], l[1]);
    fsplit2(v.z, h[2], l[2]); fsplit2(v.w, h[3], l[3]);
    *(uint2*)(hi + i) = *(uint2*)h;
    *(uint2*)(lo + i) = *(uint2*)l;
}

// ---------------- weight transpose + split: Wt[n][k] = W[k][n] ----------------
__global__ void transpose_split_kernel(const float* __restrict__ W,
                                       bf16* __restrict__ Wh, bf16* __restrict__ Wl,
                                       int K, int N) {
    __shared__ float t[32][33];
    int x = blockIdx.x * 32 + threadIdx.x;   // n
    int y0 = blockIdx.y * 32;                // k base
#pragma unroll
    for (int i = threadIdx.y; i < 32; i += 8)
        t[i][threadIdx.x] = W[(size_t)(y0 + i) * N + x];
    __syncthreads();
    int xo = y0 + threadIdx.x;               // k
    int yo0 = blockIdx.x * 32;               // n base
#pragma unroll
    for (int i = threadIdx.y; i < 32; i += 8) {
        bf16 h, l;
        fsplit2(t[threadIdx.x][i], h, l);
        Wh[(size_t)(yo0 + i) * K + xo] = h;
        Wl[(size_t)(yo0 + i) * K + xo] = l;
    }
}

// ---------------- V transpose + split: Vt[(b,kv,d)][s] ----------------
__global__ void vtrans_kernel(const float* __restrict__ V,
                              bf16* __restrict__ Vth, bf16* __restrict__ Vtl) {
    __shared__ float t[32][33];
    const int bkv = blockIdx.z;
    const int bb = bkv >> 2, kv = bkv & 3;
    const int s0 = blockIdx.x * 32, d0 = blockIdx.y * 32;
#pragma unroll
    for (int i = threadIdx.y; i < 32; i += 8)
        t[i][threadIdx.x] = V[(size_t)(bb * SEQ + s0 + i) * (NKV * HD) + kv * HD + d0 + threadIdx.x];
    __syncthreads();
#pragma unroll
    for (int i = threadIdx.y; i < 32; i += 8) {
        bf16 h, l;
        fsplit2(t[threadIdx.x][i], h, l);
        size_t idx = (size_t)(bkv * HD + d0 + i) * SEQ + s0 + threadIdx.x;
        Vth[idx] = h; Vtl[idx] = l;
    }
}

// ---------------- bf16x3 GEMM: C[M,N] = A[M,K] @ Bt[N,K]^T, ~fp32-accurate ----------------
// hi/lo bf16 planes, K contiguous. 128x128 tile, BK=32, 8 warps x 64x32,
// 3-term m16n8k16 (hi.hi + hi.lo + lo.hi). 2-stage cp.async.
#define GROWB 80                              /* bytes per smem row (32 bf16 + pad) */
#define GPLANE (128 * GROWB)                  /* 10240 B */
#define GSTAGE_BYTES (4 * GPLANE)             /* Ah Al Bh Bl = 40960 B */
#define GM_SMEM_BYTES (2 * GSTAGE_BYTES)      /* 81920 B */

__global__ __launch_bounds__(256, 2)
void bf16x3_gemm_kernel(const bf16* __restrict__ Ah, const bf16* __restrict__ Al,
                        const bf16* __restrict__ Bh, const bf16* __restrict__ Bl,
                        float* __restrict__ C, int M, int N, int K) {
    extern __shared__ char gsm[];
    const uint32_t sbase = smem_u32(gsm);

    const int tid = threadIdx.x;
    const int wid = tid >> 5, l = tid & 31;
    const int wm = wid >> 2;        // 0..1 -> M offset wm*64
    const int wn = wid & 3;         // 0..3 -> N offset wn*32
    const int bn = blockIdx.x, bm = blockIdx.y;

    const bf16* src[4] = { Ah + (size_t)bm * 128 * K, Al + (size_t)bm * 128 * K,
                           Bh + (size_t)bn * 128 * K, Bl + (size_t)bn * 128 * K };
    const int KT = K >> 5;

    const int a_sel = l & 15;
    const uint32_t a_kB = (uint32_t)(l >> 4) * 16;
    const int b_sel = l & 7;
    const uint32_t b_kB = (uint32_t)((l >> 3) & 1) * 16;

    float acc[4][4][4];
#pragma unroll
    for (int mt = 0; mt < 4; mt++)
#pragma unroll
        for (int nt = 0; nt < 4; nt++)
#pragma unroll
            for (int r = 0; r < 4; r++) acc[mt][nt][r] = 0.f;

    auto load_stage = [&](int s, int kt) {
        uint32_t base = sbase + s * GSTAGE_BYTES;
        int k0 = kt << 5;
#pragma unroll
        for (int pl = 0; pl < 4; pl++)
#pragma unroll
            for (int half = 0; half < 2; half++) {
                int cid = half * 256 + tid;           // 0..511
                int row = cid >> 2, ch = cid & 3;
                CP_ASYNC16(base + pl * GPLANE + row * GROWB + ch * 16,
                           src[pl] + (size_t)row * K + k0 + ch * 8);
            }
    };

    load_stage(0, 0);
    CP_COMMIT();

    for (int kt = 0; kt < KT; kt++) {
        const int s = kt & 1;
        CP_WAIT(0);
        __syncthreads();
        if (kt + 1 < KT) { load_stage(s ^ 1, kt + 1); CP_COMMIT(); }

        const uint32_t base = sbase + s * GSTAGE_BYTES;

#pragma unroll
        for (int ks = 0; ks < 2; ks++) {     // 2 x k16 per BK=32
            const uint32_t kB = ks * 32;
            uint32_t bh[4][2], bl[4][2];
#pragma unroll
            for (int nt = 0; nt < 4; nt++) {
                uint32_t boff = (wn * 32 + nt * 8 + b_sel) * GROWB + kB + b_kB;
                ldsm_x2(base + 2 * GPLANE + boff, bh[nt]);
                ldsm_x2(base + 3 * GPLANE + boff, bl[nt]);
            }
#pragma unroll
            for (int mt = 0; mt < 4; mt++) {
                uint32_t ah[4], al[4];
                uint32_t aoff = (wm * 64 + mt * 16 + a_sel) * GROWB + kB + a_kB;
                ldsm_x4(base + aoff, ah);
                ldsm_x4(base + GPLANE + aoff, al);
#pragma unroll
                for (int nt = 0; nt < 4; nt++) {
                    mma_bf16(acc[mt][nt], al, bh[nt]);   // lo*hi
                    mma_bf16(acc[mt][nt], ah, bl[nt]);   // hi*lo
                    mma_bf16(acc[mt][nt], ah, bh[nt]);   // hi*hi
                }
            }
        }
        __syncthreads();
    }

    const int er = l >> 2, ec = (l & 3) * 2;
#pragma unroll
    for (int mt = 0; mt < 4; mt++) {
        int row = bm * 128 + wm * 64 + mt * 16 + er;
#pragma unroll
        for (int nt = 0; nt < 4; nt++) {
            int col = bn * 128 + wn * 32 + nt * 8 + ec;
            *(float2*)(C + (size_t)row * N + col) =
                make_float2(acc[mt][nt][0], acc[mt][nt][1]);
            *(float2*)(C + (size_t)(row + 8) * N + col) =
                make_float2(acc[mt][nt][2], acc[mt][nt][3]);
        }
    }
}

// ---------------- fused RMSNorm + RoPE, fp32 in -> bf16 hi/lo planes ----------------
__global__ void rmsnorm_rope_kernel(const float* __restrict__ X,
                                    bf16* __restrict__ Xh, bf16* __restrict__ Xl,
                                    const float* __restrict__ w,
                                    const float* __restrict__ cs, const float* __restrict__ sn,
                                    int nheads) {
    const int tok = blockIdx.x;
    const int h   = blockIdx.y;
    const int d   = threadIdx.x;
    const int s   = tok & (SEQ - 1);

    const float* row = X + (size_t)tok * nheads * HD + h * HD;
    float x = row[d];

    float ss = x * x;
#pragma unroll
    for (int o = 16; o > 0; o >>= 1) ss += __shfl_xor_sync(0xffffffffu, ss, o);

    __shared__ float wsum[4];
    __shared__ float sv[HD];
    if ((d & 31) == 0) wsum[d >> 5] = ss;
    __syncthreads();
    float tot = wsum[0] + wsum[1] + wsum[2] + wsum[3];
    float r = rsqrtf(tot * (1.0f / HD) + 1e-6f);
    float v = x * r * w[d];
    sv[d] = v;
    __syncthreads();
    float rot = (d < 64) ? -sv[d + 64] : sv[d - 64];
    float y = v * cs[(size_t)s * HD + d] + rot * sn[(size_t)s * HD + d];
    bf16 hh, ll;
    fsplit2(y, hh, ll);
    size_t idx = (size_t)tok * nheads * HD + h * HD + d;
    Xh[idx] = hh; Xl[idx] = ll;
}

// ---------------- tensor-core causal flash attention (bf16x3), GQA ----------------
// CTA: 128 q rows; per-iter 64 kv. 8 warps: wm=wid>>1 (4), wn=wid&1 (2).
// byte offsets in dynamic smem:
#define FQ_S 272                       /* Q/K row stride bytes (128 bf16 + pad) */
#define FV_S 144                       /* V/P row stride bytes (64 bf16 + pad) */
#define OFF_QH 0
#define OFF_QL (OFF_QH + 128 * FQ_S)
#define OFF_KH (OFF_QL + 128 * FQ_S)
#define OFF_KL (OFF_KH + 64 * FQ_S)
#define OFF_VH (OFF_KL + 64 * FQ_S)
#define OFF_VL (OFF_VH + 128 * FV_S)
#define OFF_PH (OFF_VL + 128 * FV_S)
#define OFF_PL (OFF_PH + 128 * FV_S)
#define OFF_RM (OFF_PL + 128 * FV_S)
#define OFF_RS (OFF_RM + 1024)
#define FLASH_SMEM_BYTES (OFF_RS + 1024)

__global__ __launch_bounds__(256, 1)
void flash_kernel(const bf16* __restrict__ Qh, const bf16* __restrict__ Ql,
                  const bf16* __restrict__ Kh, const bf16* __restrict__ Kl,
                  const bf16* __restrict__ Vth, const bf16* __restrict__ Vtl,
                  bf16* __restrict__ Oh, bf16* __restrict__ Ol) {
    extern __shared__ char fsmc[];
    const uint32_t sb = smem_u32(fsmc);
    bf16* smb = (bf16*)fsmc;
    float* redm = (float*)(fsmc + OFF_RM);
    float* reds = (float*)(fsmc + OFF_RS);

    const int qt = blockIdx.x, h = blockIdx.y, b = blockIdx.z;
    const int kvh = h >> 2;
    const int tid = threadIdx.x, wid = tid >> 5, l = tid & 31;
    const int wm = wid >> 1, wn = wid & 1;
    const float scale = 0.08838834764831845f;

    const int a_sel = l & 15;
    const uint32_t a_kB = (uint32_t)(l >> 4) * 16;
    const int b_sel = l & 7;
    const uint32_t b_kB = (uint32_t)((l >> 3) & 1) * 16;
    const int qrow = l >> 2, qcol = (l & 3) * 2;

    // Q tiles (both planes), once: 4096 chunks
    {
        const bf16* qsrc[2] = { Qh + (size_t)(b * SEQ + qt * 128) * (NH * HD) + h * HD,
                                Ql + (size_t)(b * SEQ + qt * 128) * (NH * HD) + h * HD };
#pragma unroll
        for (int t = 0; t < 16; t++) {
            int c = tid + t * 256;
            int pl = c >> 11, cid = c & 2047;
            int r = cid >> 4, ch = cid & 15;
            CP_ASYNC16(sb + OFF_QH + pl * (128 * FQ_S) + r * FQ_S + ch * 16,
                       qsrc[pl] + (size_t)r * (NH * HD) + ch * 8);
        }
    }
    CP_COMMIT();

    const bf16* ksrc[2] = { Kh + (size_t)(b * SEQ) * (NKV * HD) + kvh * HD,
                            Kl + (size_t)(b * SEQ) * (NKV * HD) + kvh * HD };
    const bf16* vsrc[2] = { Vth + (size_t)(b * NKV + kvh) * HD * SEQ,
                            Vtl + (size_t)(b * NKV + kvh) * HD * SEQ };

    float m[2][2], lsum[2][2], oacc[2][8][4];
#pragma unroll
    for (int mt = 0; mt < 2; mt++)
#pragma unroll
        for (int h2 = 0; h2 < 2; h2++) { m[mt][h2] = -1e30f; lsum[mt][h2] = 0.f; }
#pragma unroll
    for (int mt = 0; mt < 2; mt++)
#pragma unroll
        for (int nto = 0; nto < 8; nto++)
#pragma unroll
            for (int e = 0; e < 4; e++) oacc[mt][nto][e] = 0.f;

    const int jt_end = 2 * qt + 2;
    for (int jt = 0; jt < jt_end; jt++) {
        // K planes: 2048 chunks; V planes: 2048 chunks
#pragma unroll
        for (int t = 0; t < 8; t++) {
            int c = tid + t * 256;
            int pl = c >> 10, cid = c & 1023;
            int r = cid >> 4, ch = cid & 15;
            CP_ASYNC16(sb + OFF_KH + pl * (64 * FQ_S) + r * FQ_S + ch * 16,
                       ksrc[pl] + (size_t)(jt * 64 + r) * (NKV * HD) + ch * 8);
        }
#pragma unroll
        for (int t = 0; t < 8; t++) {
            int c = tid + t * 256;
            int pl = c >> 10, cid = c & 1023;
            int r = cid >> 3, ch = cid & 7;
            CP_ASYNC16(sb + OFF_VH + pl * (128 * FV_S) + r * FV_S + ch * 16,
                       vsrc[pl] + (size_t)r * SEQ + jt * 64 + ch * 8);
        }
        CP_COMMIT(); CP_WAIT(0); __syncthreads();

        // S = Q @ K^T (8 k16 steps), 3-term
        float sacc[2][4][4];
#pragma unroll
        for (int mt = 0; mt < 2; mt++)
#pragma unroll
            for (int nt = 0; nt < 4; nt++)
#pragma unroll
                for (int e = 0; e < 4; e++) sacc[mt][nt][e] = 0.f;

#pragma unroll
        for (int ks = 0; ks < 8; ks++) {
            const uint32_t kB = ks * 32;
            uint32_t bh[4][2], bl[4][2];
#pragma unroll
            for (int nt = 0; nt < 4; nt++) {
                uint32_t boff = (wn * 32 + nt * 8 + b_sel) * FQ_S + kB + b_kB;
                ldsm_x2(sb + OFF_KH + boff, bh[nt]);
                ldsm_x2(sb + OFF_KL + boff, bl[nt]);
            }
#pragma unroll
            for (int mt = 0; mt < 2; mt++) {
                uint32_t ah[4], al[4];
                uint32_t aoff = (wm * 32 + mt * 16 + a_sel) * FQ_S + kB + a_kB;
                ldsm_x4(sb + OFF_QH + aoff, ah);
                ldsm_x4(sb + OFF_QL + aoff, al);
#pragma unroll
                for (int nt = 0; nt < 4; nt++) {
                    mma_bf16(sacc[mt][nt], al, bh[nt]);
                    mma_bf16(sacc[mt][nt], ah, bl[nt]);
                    mma_bf16(sacc[mt][nt], ah, bh[nt]);
                }
            }
        }

        // scale + causal mask + row max
        const bool need_mask = (jt >= 2 * qt);
        float lmax[2][2];
#pragma unroll
        for (int mt = 0; mt < 2; mt++)
#pragma unroll
            for (int h2 = 0; h2 < 2; h2++) lmax[mt][h2] = -1e30f;
#pragma unroll
        for (int mt = 0; mt < 2; mt++)
#pragma unroll
            for (int nt = 0; nt < 4; nt++)
#pragma unroll
                for (int e = 0; e < 4; e++) {
                    int h2 = e >> 1, j = e & 1;
                    float val = sacc[mt][nt][e] * scale;
                    if (need_mask) {
                        int gr = qt * 128 + wm * 32 + mt * 16 + qrow + 8 * h2;
                        int gc = jt * 64 + wn * 32 + nt * 8 + qcol + j;
                        if (gc > gr) val = -1e30f;
                    }
                    sacc[mt][nt][e] = val;
                    lmax[mt][h2] = fmaxf(lmax[mt][h2], val);
                }
#pragma unroll
        for (int mt = 0; mt < 2; mt++)
#pragma unroll
            for (int h2 = 0; h2 < 2; h2++) {
                float v = lmax[mt][h2];
                v = fmaxf(v, __shfl_xor_sync(0xffffffffu, v, 1));
                v = fmaxf(v, __shfl_xor_sync(0xffffffffu, v, 2));
                lmax[mt][h2] = v;
            }
        if ((l & 3) == 0) {
#pragma unroll
            for (int mt = 0; mt < 2; mt++)
#pragma unroll
                for (int h2 = 0; h2 < 2; h2++)
                    redm[wn * 128 + wm * 32 + mt * 16 + qrow + 8 * h2] = lmax[mt][h2];
        }
        __syncthreads();

        float alpha[2][2];
#pragma unroll
        for (int mt = 0; mt < 2; mt++)
#pragma unroll
            for (int h2 = 0; h2 < 2; h2++) {
                int r = wm * 32 + mt * 16 + qrow + 8 * h2;
                float tm = fmaxf(redm[r], redm[128 + r]);
                float mn = fmaxf(m[mt][h2], tm);
                alpha[mt][h2] = __expf(m[mt][h2] - mn);
                m[mt][h2] = mn;
            }

        // p = exp(s - m), local sums, write P planes
        float ls[2][2] = {{0.f, 0.f}, {0.f, 0.f}};
#pragma unroll
        for (int mt = 0; mt < 2; mt++)
#pragma unroll
            for (int nt = 0; nt < 4; nt++)
#pragma unroll
                for (int e = 0; e < 4; e++) {
                    int h2 = e >> 1, j = e & 1;
                    float p = __expf(sacc[mt][nt][e] - m[mt][h2]);
                    ls[mt][h2] += p;
                    int r = wm * 32 + mt * 16 + qrow + 8 * h2;
                    int c = wn * 32 + nt * 8 + qcol + j;
                    bf16 ph, pl;
                    fsplit2(p, ph, pl);
                    smb[(OFF_PH >> 1) + r * (FV_S >> 1) + c] = ph;
                    smb[(OFF_PL >> 1) + r * (FV_S >> 1) + c] = pl;
                }
#pragma unroll
        for (int mt = 0; mt < 2; mt++)
#pragma unroll
            for (int h2 = 0; h2 < 2; h2++) {
                float v = ls[mt][h2];
                v += __shfl_xor_sync(0xffffffffu, v, 1);
                v += __shfl_xor_sync(0xffffffffu, v, 2);
                ls[mt][h2] = v;
            }
        if ((l & 3) == 0) {
#pragma unroll
            for (int mt = 0; mt < 2; mt++)
#pragma unroll
                for (int h2 = 0; h2 < 2; h2++)
                    reds[wn * 128 + wm * 32 + mt * 16 + qrow + 8 * h2] = ls[mt][h2];
        }

        // rescale O accumulators
#pragma unroll
        for (int mt = 0; mt < 2; mt++)
#pragma unroll
            for (int nto = 0; nto < 8; nto++)
#pragma unroll
                for (int e = 0; e < 4; e++)
                    oacc[mt][nto][e] *= alpha[mt][e >> 1];
        __syncthreads();

#pragma unroll
        for (int mt = 0; mt < 2; mt++)
#pragma unroll
            for (int h2 = 0; h2 < 2; h2++) {
                int r = wm * 32 + mt * 16 + qrow + 8 * h2;
                lsum[mt][h2] = lsum[mt][h2] * alpha[mt][h2] + reds[r] + reds[128 + r];
            }

        // O += P @ V (4 k16 steps), 3-term
#pragma unroll
        for (int ks = 0; ks < 4; ks++) {
            const uint32_t kB = ks * 32;
            uint32_t pf[2][4], pg[2][4];
#pragma unroll
            for (int mt = 0; mt < 2; mt++) {
                uint32_t aoff = (wm * 32 + mt * 16 + a_sel) * FV_S + kB + a_kB;
                ldsm_x4(sb + OFF_PH + aoff, pf[mt]);
                ldsm_x4(sb + OFF_PL + aoff, pg[mt]);
            }
#pragma unroll
            for (int nto = 0; nto < 8; nto++) {
                uint32_t vh[2], vl[2];
                uint32_t boff = (wn * 64 + nto * 8 + b_sel) * FV_S + kB + b_kB;
                ldsm_x2(sb + OFF_VH + boff, vh);
                ldsm_x2(sb + OFF_VL + boff, vl);
#pragma unroll
                for (int mt = 0; mt < 2; mt++) {
                    mma_bf16(oacc[mt][nto], pg[mt], vh);
                    mma_bf16(oacc[mt][nto], pf[mt], vl);
                    mma_bf16(oacc[mt][nto], pf[mt], vh);
                }
            }
        }
        __syncthreads();
    }

    // epilogue: normalize, split, store hi/lo planes
    bf16* Ogh = Oh + (size_t)(b * SEQ + qt * 128) * (NH * HD) + h * HD;
    bf16* Ogl = Ol + (size_t)(b * SEQ + qt * 128) * (NH * HD) + h * HD;
#pragma unroll
    for (int mt = 0; mt < 2; mt++)
#pragma unroll
        for (int h2 = 0; h2 < 2; h2++) {
            int r = wm * 32 + mt * 16 + qrow + 8 * h2;
            float inv = 1.0f / lsum[mt][h2];
#pragma unroll
            for (int nto = 0; nto < 8; nto++) {
                int c = wn * 64 + nto * 8 + qcol;
                bf16 h0, l0, h1, l1;
                fsplit2(oacc[mt][nto][h2 * 2 + 0] * inv, h0, l0);
                fsplit2(oacc[mt][nto][h2 * 2 + 1] * inv, h1, l1);
                bf16 hp[2] = { h0, h1 }, lp[2] = { l0, l1 };
                *(uint32_t*)(Ogh + (size_t)r * (NH * HD) + c) = *(uint32_t*)hp;
                *(uint32_t*)(Ogl + (size_t)r * (NH * HD) + c) = *(uint32_t*)lp;
            }
        }
}

// ---------------- launch ----------------
extern "C" void kernel_launch(void* const* d_in, const int* in_sizes, int n_in,
                              void* d_out, int out_size) {
    const float* X  = (const float*)d_in[0];
    const float* cs = (const float*)d_in[1];
    const float* sn = (const float*)d_in[2];
    const float* Wq = (const float*)d_in[3];
    const float* Wk = (const float*)d_in[4];
    const float* Wv = (const float*)d_in[5];
    const float* Wo = (const float*)d_in[6];
    const float* qw = (const float*)d_in[7];
    const float* kw = (const float*)d_in[8];
    float* out = (float*)d_out;

    float *Q, *K, *V;
    bf16 *Xh, *Xl, *Qh, *Ql, *Kh, *Kl, *Vth, *Vtl, *Oh, *Ol;
    bf16 *WqTh, *WqTl, *WkTh, *WkTl, *WvTh, *WvTl, *WoTh, *WoTl;
    cudaGetSymbolAddress((void**)&Q,  g_Q);
    cudaGetSymbolAddress((void**)&K,  g_K);
    cudaGetSymbolAddress((void**)&V,  g_V);
    cudaGetSymbolAddress((void**)&Xh, g_Xh);  cudaGetSymbolAddress((void**)&Xl, g_Xl);
    cudaGetSymbolAddress((void**)&Qh, g_Qh);  cudaGetSymbolAddress((void**)&Ql, g_Ql);
    cudaGetSymbolAddress((void**)&Kh, g_Kh);  cudaGetSymbolAddress((void**)&Kl, g_Kl);
    cudaGetSymbolAddress((void**)&Vth, g_Vth); cudaGetSymbolAddress((void**)&Vtl, g_Vtl);
    cudaGetSymbolAddress((void**)&Oh, g_Oh);  cudaGetSymbolAddress((void**)&Ol, g_Ol);
    cudaGetSymbolAddress((void**)&WqTh, g_WqTh); cudaGetSymbolAddress((void**)&WqTl, g_WqTl);
    cudaGetSymbolAddress((void**)&WkTh, g_WkTh); cudaGetSymbolAddress((void**)&WkTl, g_WkTl);
    cudaGetSymbolAddress((void**)&WvTh, g_WvTh); cudaGetSymbolAddress((void**)&WvTl, g_WvTl);
    cudaGetSymbolAddress((void**)&WoTh, g_WoTh); cudaGetSymbolAddress((void**)&WoTl, g_WoTl);

    cudaFuncSetAttribute(bf16x3_gemm_kernel, cudaFuncAttributeMaxDynamicSharedMemorySize,
                         GM_SMEM_BYTES);
    cudaFuncSetAttribute(flash_kernel, cudaFuncAttributeMaxDynamicSharedMemorySize,
                         FLASH_SMEM_BYTES);

    // operand preparation
    split_kernel<<<(TOKENS * HID) / 1024, 256>>>(X, Xh, Xl);
    transpose_split_kernel<<<dim3(2048 / 32, 2048 / 32), dim3(32, 8)>>>(Wq, WqTh, WqTl, 2048, 2048);
    transpose_split_kernel<<<dim3( 512 / 32, 2048 / 32), dim3(32, 8)>>>(Wk, WkTh, WkTl, 2048,  512);
    transpose_split_kernel<<<dim3( 512 / 32, 2048 / 32), dim3(32, 8)>>>(Wv, WvTh, WvTl, 2048,  512);
    transpose_split_kernel<<<dim3(2048 / 32, 2048 / 32), dim3(32, 8)>>>(Wo, WoTh, WoTl, 2048, 2048);

    // QKV projections (bf16x3 tensor GEMM)
    bf16x3_gemm_kernel<<<dim3(2048 / 128, TOKENS / 128), 256, GM_SMEM_BYTES>>>(
        Xh, Xl, WqTh, WqTl, Q, TOKENS, 2048, HID);
    bf16x3_gemm_kernel<<<dim3( 512 / 128, TOKENS / 128), 256, GM_SMEM_BYTES>>>(
        Xh, Xl, WkTh, WkTl, K, TOKENS,  512, HID);
    bf16x3_gemm_kernel<<<dim3( 512 / 128, TOKENS / 128), 256, GM_SMEM_BYTES>>>(
        Xh, Xl, WvTh, WvTl, V, TOKENS,  512, HID);

    // RMSNorm + RoPE -> planes; V transpose + split
    rmsnorm_rope_kernel<<<dim3(TOKENS, NH),  HD>>>(Q, Qh, Ql, qw, cs, sn, NH);
    rmsnorm_rope_kernel<<<dim3(TOKENS, NKV), HD>>>(K, Kh, Kl, kw, cs, sn, NKV);
    vtrans_kernel<<<dim3(SEQ / 32, HD / 32, BATCH * NKV), dim3(32, 8)>>>(V, Vth, Vtl);

    // causal GQA flash attention (bf16x3 tensor core)
    flash_kernel<<<dim3(SEQ / 128, NH, BATCH), 256, FLASH_SMEM_BYTES>>>(
        Qh, Ql, Kh, Kl, Vth, Vtl, Oh, Ol);

    // output projection
    bf16x3_gemm_kernel<<<dim3(2048 / 128, TOKENS / 128), 256, GM_SMEM_BYTES>>>(
        Oh, Ol, WoTh, WoTl, out, TOKENS, 2048, HID);
}

// round 14
// speedup vs baseline: 2.6982x; 1.0689x over previous
#include <cuda_runtime.h>
#include <cuda_bf16.h>
#include <math.h>
#include <stdint.h>

typedef __nv_bfloat16 bf16;

#define HID   2048
#define NH    16
#define NKV   4
#define HD    128
#define SEQ   2048
#define BATCH 2
#define TOKENS (BATCH*SEQ)
#define NC    3072   /* concatenated QKV output width */

// ---------------- scratch (no allocation allowed) ----------------
__device__ float g_C[(size_t)TOKENS * NC];                 // fused QKV GEMM out
__device__ bf16  g_Xh[(size_t)TOKENS * HID],      g_Xl[(size_t)TOKENS * HID];
__device__ bf16  g_Qh[(size_t)TOKENS * NH * HD],  g_Ql[(size_t)TOKENS * NH * HD];
__device__ bf16  g_Kh[(size_t)TOKENS * NKV * HD], g_Kl[(size_t)TOKENS * NKV * HD];
__device__ bf16  g_Vth[(size_t)BATCH * NKV * HD * SEQ], g_Vtl[(size_t)BATCH * NKV * HD * SEQ];
__device__ bf16  g_Oh[(size_t)TOKENS * NH * HD],  g_Ol[(size_t)TOKENS * NH * HD];
__device__ bf16  g_WcTh[(size_t)NC * 2048],  g_WcTl[(size_t)NC * 2048];   // Wq|Wk|Wv transposed
__device__ bf16  g_WoTh[(size_t)2048 * 2048], g_WoTl[(size_t)2048 * 2048];

// ---------------- helpers ----------------
__device__ __forceinline__ uint32_t smem_u32(const void* p) {
    uint32_t a;
    asm("{ .reg .u64 t; cvta.to.shared.u64 t, %1; cvt.u32.u64 %0, t; }" : "=r"(a) : "l"(p));
    return a;
}

#define CP_ASYNC16(dst, src) \
    asm volatile("cp.async.cg.shared.global [%0], [%1], 16;" :: "r"(dst), "l"(src))
#define CP_COMMIT() asm volatile("cp.async.commit_group;" ::: "memory")
#define CP_WAIT(n)  asm volatile("cp.async.wait_group %0;" :: "n"(n) : "memory")

__device__ __forceinline__ void ldsm_x4(uint32_t addr, uint32_t r[4]) {
    asm volatile("ldmatrix.sync.aligned.m8n8.x4.shared.b16 {%0,%1,%2,%3}, [%4];"
                 : "=r"(r[0]), "=r"(r[1]), "=r"(r[2]), "=r"(r[3]) : "r"(addr));
}
__device__ __forceinline__ void ldsm_x2(uint32_t addr, uint32_t r[2]) {
    asm volatile("ldmatrix.sync.aligned.m8n8.x2.shared.b16 {%0,%1}, [%2];"
                 : "=r"(r[0]), "=r"(r[1]) : "r"(addr));
}
__device__ __forceinline__ void mma_bf16(float c[4], const uint32_t a[4], const uint32_t b[2]) {
    asm volatile(
        "mma.sync.aligned.m16n8k16.row.col.f32.bf16.bf16.f32 "
        "{%0,%1,%2,%3}, {%4,%5,%6,%7}, {%8,%9}, {%0,%1,%2,%3};"
        : "+f"(c[0]), "+f"(c[1]), "+f"(c[2]), "+f"(c[3])
        : "r"(a[0]), "r"(a[1]), "r"(a[2]), "r"(a[3]), "r"(b[0]), "r"(b[1]));
}

__device__ __forceinline__ void fsplit2(float x, bf16& h, bf16& l) {
    h = __float2bfloat16(x);
    l = __float2bfloat16(x - __bfloat162float(h));
}
__device__ __forceinline__ uint32_t pack2(bf16 lo, bf16 hi) {
    __nv_bfloat162 t; t.x = lo; t.y = hi;
    return *reinterpret_cast<uint32_t*>(&t);
}

// ---------------- elementwise split: fp32 -> hi/lo planes ----------------
__global__ void split_kernel(const float* __restrict__ in,
                             bf16* __restrict__ hi, bf16* __restrict__ lo) {
    int i = (blockIdx.x * 256 + threadIdx.x) * 4;
    float4 v = *(const float4*)(in + i);
    bf16 h[4], l[4];
    fsplit2(v.x, h[0], l[0]); fsplit2(v.y, h[1], l[1]);
    fsplit2(v.z, h[2], l[2]); fsplit2(v.w, h[3], l[3]);
    *(uint2*)(hi + i) = *(uint2*)h;
    *(uint2*)(lo + i) = *(uint2*)l;
}

// ---------------- weight transpose + split: Wt[n][k] = W[k][n] ----------------
__global__ void transpose_split_kernel(const float* __restrict__ W,
                                       bf16* __restrict__ Wh, bf16* __restrict__ Wl,
                                       int K, int N) {
    __shared__ float t[32][33];
    int x = blockIdx.x * 32 + threadIdx.x;   // n
    int y0 = blockIdx.y * 32;                // k base
#pragma unroll
    for (int i = threadIdx.y; i < 32; i += 8)
        t[i][threadIdx.x] = W[(size_t)(y0 + i) * N + x];
    __syncthreads();
    int xo = y0 + threadIdx.x;               // k
    int yo0 = blockIdx.x * 32;               // n base
#pragma unroll
    for (int i = threadIdx.y; i < 32; i += 8) {
        bf16 h, l;
        fsplit2(t[threadIdx.x][i], h, l);
        Wh[(size_t)(yo0 + i) * K + xo] = h;
        Wl[(size_t)(yo0 + i) * K + xo] = l;
    }
}

// ---------------- V transpose + split from fused C: Vt[(b,kv,d)][s] ----------------
__global__ void vtrans_kernel(const float* __restrict__ C,
                              bf16* __restrict__ Vth, bf16* __restrict__ Vtl) {
    __shared__ float t[32][33];
    const int bkv = blockIdx.z;
    const int bb = bkv >> 2, kv = bkv & 3;
    const int s0 = blockIdx.x * 32, d0 = blockIdx.y * 32;
#pragma unroll
    for (int i = threadIdx.y; i < 32; i += 8)
        t[i][threadIdx.x] = C[(size_t)(bb * SEQ + s0 + i) * NC + 2560 + kv * HD + d0 + threadIdx.x];
    __syncthreads();
#pragma unroll
    for (int i = threadIdx.y; i < 32; i += 8) {
        bf16 h, l;
        fsplit2(t[threadIdx.x][i], h, l);
        size_t idx = (size_t)(bkv * HD + d0 + i) * SEQ + s0 + threadIdx.x;
        Vth[idx] = h; Vtl[idx] = l;
    }
}

// ---------------- bf16x3 GEMM: C[M,N] = A[M,K] @ Bt[N,K]^T ----------------
#define GROWB 80
#define GPLANE (128 * GROWB)
#define GSTAGE_BYTES (4 * GPLANE)
#define GM_SMEM_BYTES (2 * GSTAGE_BYTES)

__global__ __launch_bounds__(256, 2)
void bf16x3_gemm_kernel(const bf16* __restrict__ Ah, const bf16* __restrict__ Al,
                        const bf16* __restrict__ Bh, const bf16* __restrict__ Bl,
                        float* __restrict__ C, int M, int N, int K) {
    extern __shared__ char gsm[];
    const uint32_t sbase = smem_u32(gsm);

    const int tid = threadIdx.x;
    const int wid = tid >> 5, l = tid & 31;
    const int wm = wid >> 2, wn = wid & 3;
    const int bn = blockIdx.x, bm = blockIdx.y;

    const bf16* src[4] = { Ah + (size_t)bm * 128 * K, Al + (size_t)bm * 128 * K,
                           Bh + (size_t)bn * 128 * K, Bl + (size_t)bn * 128 * K };
    const int KT = K >> 5;

    const int a_sel = l & 15;
    const uint32_t a_kB = (uint32_t)(l >> 4) * 16;
    const int b_sel = l & 7;
    const uint32_t b_kB = (uint32_t)((l >> 3) & 1) * 16;

    float acc[4][4][4];
#pragma unroll
    for (int mt = 0; mt < 4; mt++)
#pragma unroll
        for (int nt = 0; nt < 4; nt++)
#pragma unroll
            for (int r = 0; r < 4; r++) acc[mt][nt][r] = 0.f;

    auto load_stage = [&](int s, int kt) {
        uint32_t base = sbase + s * GSTAGE_BYTES;
        int k0 = kt << 5;
#pragma unroll
        for (int pl = 0; pl < 4; pl++)
#pragma unroll
            for (int half = 0; half < 2; half++) {
                int cid = half * 256 + tid;
                int row = cid >> 2, ch = cid & 3;
                CP_ASYNC16(base + pl * GPLANE + row * GROWB + ch * 16,
                           src[pl] + (size_t)row * K + k0 + ch * 8);
            }
    };

    load_stage(0, 0);
    CP_COMMIT();

    for (int kt = 0; kt < KT; kt++) {
        const int s = kt & 1;
        CP_WAIT(0);
        __syncthreads();
        if (kt + 1 < KT) { load_stage(s ^ 1, kt + 1); CP_COMMIT(); }

        const uint32_t base = sbase + s * GSTAGE_BYTES;

#pragma unroll
        for (int ks = 0; ks < 2; ks++) {
            const uint32_t kB = ks * 32;
            uint32_t bh[4][2], bl[4][2];
#pragma unroll
            for (int nt = 0; nt < 4; nt++) {
                uint32_t boff = (wn * 32 + nt * 8 + b_sel) * GROWB + kB + b_kB;
                ldsm_x2(base + 2 * GPLANE + boff, bh[nt]);
                ldsm_x2(base + 3 * GPLANE + boff, bl[nt]);
            }
#pragma unroll
            for (int mt = 0; mt < 4; mt++) {
                uint32_t ah[4], al[4];
                uint32_t aoff = (wm * 64 + mt * 16 + a_sel) * GROWB + kB + a_kB;
                ldsm_x4(base + aoff, ah);
                ldsm_x4(base + GPLANE + aoff, al);
#pragma unroll
                for (int nt = 0; nt < 4; nt++) {
                    mma_bf16(acc[mt][nt], al, bh[nt]);
                    mma_bf16(acc[mt][nt], ah, bl[nt]);
                    mma_bf16(acc[mt][nt], ah, bh[nt]);
                }
            }
        }
        __syncthreads();
    }

    const int er = l >> 2, ec = (l & 3) * 2;
#pragma unroll
    for (int mt = 0; mt < 4; mt++) {
        int row = bm * 128 + wm * 64 + mt * 16 + er;
#pragma unroll
        for (int nt = 0; nt < 4; nt++) {
            int col = bn * 128 + wn * 32 + nt * 8 + ec;
            *(float2*)(C + (size_t)row * N + col) =
                make_float2(acc[mt][nt][0], acc[mt][nt][1]);
            *(float2*)(C + (size_t)(row + 8) * N + col) =
                make_float2(acc[mt][nt][2], acc[mt][nt][3]);
        }
    }
}

// ---------------- fused RMSNorm + RoPE (reads fused C) -> bf16 hi/lo planes ----------------
__global__ void rmsnorm_rope_kernel(const float* __restrict__ C, int in_off,
                                    bf16* __restrict__ Xh, bf16* __restrict__ Xl,
                                    const float* __restrict__ w,
                                    const float* __restrict__ cs, const float* __restrict__ sn,
                                    int nheads) {
    const int tok = blockIdx.x;
    const int h   = blockIdx.y;
    const int d   = threadIdx.x;
    const int s   = tok & (SEQ - 1);

    const float* row = C + (size_t)tok * NC + in_off + h * HD;
    float x = row[d];

    float ss = x * x;
#pragma unroll
    for (int o = 16; o > 0; o >>= 1) ss += __shfl_xor_sync(0xffffffffu, ss, o);

    __shared__ float wsum[4];
    __shared__ float sv[HD];
    if ((d & 31) == 0) wsum[d >> 5] = ss;
    __syncthreads();
    float tot = wsum[0] + wsum[1] + wsum[2] + wsum[3];
    float r = rsqrtf(tot * (1.0f / HD) + 1e-6f);
    float v = x * r * w[d];
    sv[d] = v;
    __syncthreads();
    float rot = (d < 64) ? -sv[d + 64] : sv[d - 64];
    float y = v * cs[(size_t)s * HD + d] + rot * sn[(size_t)s * HD + d];
    bf16 hh, ll;
    fsplit2(y, hh, ll);
    size_t idx = (size_t)tok * nheads * HD + h * HD + d;
    Xh[idx] = hh; Xl[idx] = ll;
}

// ---------------- tensor-core causal flash attention (bf16x3), warp-owned rows ----------------
// CTA: 128 q rows, 8 warps x 16 rows. Per iter: 64 kv, double-buffered cp.async.
// P kept in registers (C-fragment -> A-fragment reuse). All softmax warp-local.
#define FQ_S 272                              /* Q/K row stride bytes */
#define FV_S 144                              /* V row stride bytes */
#define QPL (128 * FQ_S)                      /* 34816 per Q plane */
#define KPL (64 * FQ_S)                       /* 17408 per K plane */
#define VPL (128 * FV_S)                      /* 18432 per V plane */
#define OFF_K0 (2 * QPL)
#define KV_STAGE (2 * KPL + 2 * VPL)          /* 71680 */
#define FLASH_SMEM_BYTES (2 * QPL + 2 * KV_STAGE)   /* 212992 */

__global__ __launch_bounds__(256, 1)
void flash_kernel(const bf16* __restrict__ Qh, const bf16* __restrict__ Ql,
                  const bf16* __restrict__ Kh, const bf16* __restrict__ Kl,
                  const bf16* __restrict__ Vth, const bf16* __restrict__ Vtl,
                  bf16* __restrict__ Oh, bf16* __restrict__ Ol) {
    extern __shared__ char fsmc[];
    const uint32_t sb = smem_u32(fsmc);

    const int qt = blockIdx.x, h = blockIdx.y, b = blockIdx.z;
    const int kvh = h >> 2;
    const int tid = threadIdx.x, wid = tid >> 5, l = tid & 31;
    const float scale = 0.08838834764831845f;

    const int a_sel = l & 15;
    const uint32_t a_kB = (uint32_t)(l >> 4) * 16;
    const int b4 = ((l >> 4) & 1) * 8 + (l & 7);       // x4 B: two n8 tiles per load
    const uint32_t b_kB = (uint32_t)((l >> 3) & 1) * 16;
    const int qrow = l >> 2, qcol = (l & 3) * 2;

    // Q tiles (both planes), once
    {
        const bf16* qsrc[2] = { Qh + (size_t)(b * SEQ + qt * 128) * (NH * HD) + h * HD,
                                Ql + (size_t)(b * SEQ + qt * 128) * (NH * HD) + h * HD };
#pragma unroll
        for (int t = 0; t < 16; t++) {
            int c = tid + t * 256;
            int pl = c >> 11, cid = c & 2047;
            int r = cid >> 4, ch = cid & 15;
            CP_ASYNC16(sb + pl * QPL + r * FQ_S + ch * 16,
                       qsrc[pl] + (size_t)r * (NH * HD) + ch * 8);
        }
    }
    CP_COMMIT();

    const bf16* ksrc[2] = { Kh + (size_t)(b * SEQ) * (NKV * HD) + kvh * HD,
                            Kl + (size_t)(b * SEQ) * (NKV * HD) + kvh * HD };
    const bf16* vsrc[2] = { Vth + (size_t)(b * NKV + kvh) * HD * SEQ,
                            Vtl + (size_t)(b * NKV + kvh) * HD * SEQ };

    auto load_kv = [&](int jt, int st) {
        uint32_t kb = sb + OFF_K0 + st * KV_STAGE;
        uint32_t vb = kb + 2 * KPL;
#pragma unroll
        for (int t = 0; t < 8; t++) {
            int c = tid + t * 256;
            int pl = c >> 10, cid = c & 1023;
            int r = cid >> 4, ch = cid & 15;
            CP_ASYNC16(kb + pl * KPL + r * FQ_S + ch * 16,
                       ksrc[pl] + (size_t)(jt * 64 + r) * (NKV * HD) + ch * 8);
        }
#pragma unroll
        for (int t = 0; t < 8; t++) {
            int c = tid + t * 256;
            int pl = c >> 10, cid = c & 1023;
            int r = cid >> 3, ch = cid & 7;
            CP_ASYNC16(vb + pl * VPL + r * FV_S + ch * 16,
                       vsrc[pl] + (size_t)r * SEQ + jt * 64 + ch * 8);
        }
    };
    load_kv(0, 0);
    CP_COMMIT();

    float m[2] = { -1e30f, -1e30f }, lsum[2] = { 0.f, 0.f };
    float oacc[16][4];
#pragma unroll
    for (int nto = 0; nto < 16; nto++)
#pragma unroll
        for (int e = 0; e < 4; e++) oacc[nto][e] = 0.f;

    const int jt_end = 2 * qt + 2;
    for (int jt = 0; jt < jt_end; jt++) {
        const int st = jt & 1;
        CP_WAIT(0);
        __syncthreads();
        if (jt + 1 < jt_end) { load_kv(jt + 1, st ^ 1); CP_COMMIT(); }
        const uint32_t kb = sb + OFF_K0 + st * KV_STAGE;
        const uint32_t vb = kb + 2 * KPL;

        // S = Q @ K^T : warp stripe 16x64, 8 k16 steps, 3-term
        float sacc[8][4];
#pragma unroll
        for (int nt = 0; nt < 8; nt++)
#pragma unroll
            for (int e = 0; e < 4; e++) sacc[nt][e] = 0.f;

#pragma unroll
        for (int ks = 0; ks < 8; ks++) {
            const uint32_t kB = ks * 32;
            uint32_t ah[4], al[4];
            uint32_t aoff = (uint32_t)(wid * 16 + a_sel) * FQ_S + kB + a_kB;
            ldsm_x4(sb + aoff, ah);
            ldsm_x4(sb + QPL + aoff, al);
#pragma unroll
            for (int ntp = 0; ntp < 4; ntp++) {
                uint32_t bh4[4], bl4[4];
                uint32_t boff = (uint32_t)(ntp * 16 + b4) * FQ_S + kB + b_kB;
                ldsm_x4(kb + boff, bh4);
                ldsm_x4(kb + KPL + boff, bl4);
                mma_bf16(sacc[2 * ntp],     al, bh4);
                mma_bf16(sacc[2 * ntp],     ah, bl4);
                mma_bf16(sacc[2 * ntp],     ah, bh4);
                mma_bf16(sacc[2 * ntp + 1], al, bh4 + 2);
                mma_bf16(sacc[2 * ntp + 1], ah, bl4 + 2);
                mma_bf16(sacc[2 * ntp + 1], ah, bh4 + 2);
            }
        }

        // scale + causal mask + warp-local row max
        const bool need_mask = (jt >= 2 * qt);
        float lmax[2] = { -1e30f, -1e30f };
#pragma unroll
        for (int nt = 0; nt < 8; nt++)
#pragma unroll
            for (int e = 0; e < 4; e++) {
                int h2 = e >> 1;
                float val = sacc[nt][e] * scale;
                if (need_mask) {
                    int gr = qt * 128 + wid * 16 + qrow + 8 * h2;
                    int gc = jt * 64 + nt * 8 + qcol + (e & 1);
                    if (gc > gr) val = -1e30f;
                }
                sacc[nt][e] = val;
                lmax[h2] = fmaxf(lmax[h2], val);
            }

        float alpha[2];
#pragma unroll
        for (int h2 = 0; h2 < 2; h2++) {
            float v = lmax[h2];
            v = fmaxf(v, __shfl_xor_sync(0xffffffffu, v, 1));
            v = fmaxf(v, __shfl_xor_sync(0xffffffffu, v, 2));
            float mn = fmaxf(m[h2], v);
            alpha[h2] = __expf(m[h2] - mn);
            m[h2] = mn;
        }

        // p = exp(s-m): pack A-fragments (hi/lo) in registers
        float ls[2] = { 0.f, 0.f };
        uint32_t pfh[4][4], pfl[4][4];
#pragma unroll
        for (int ks2 = 0; ks2 < 4; ks2++)
#pragma unroll
            for (int half = 0; half < 2; half++) {
                int nt = 2 * ks2 + half;
                float p0 = __expf(sacc[nt][0] - m[0]);
                float p1 = __expf(sacc[nt][1] - m[0]);
                float p2 = __expf(sacc[nt][2] - m[1]);
                float p3 = __expf(sacc[nt][3] - m[1]);
                ls[0] += p0 + p1;
                ls[1] += p2 + p3;
                bf16 a0 = __float2bfloat16(p0), a1 = __float2bfloat16(p1);
                bf16 a2 = __float2bfloat16(p2), a3 = __float2bfloat16(p3);
                pfh[ks2][half * 2 + 0] = pack2(a0, a1);
                pfh[ks2][half * 2 + 1] = pack2(a2, a3);
                pfl[ks2][half * 2 + 0] =
                    pack2(__float2bfloat16(p0 - __bfloat162float(a0)),
                          __float2bfloat16(p1 - __bfloat162float(a1)));
                pfl[ks2][half * 2 + 1] =
                    pack2(__float2bfloat16(p2 - __bfloat162float(a2)),
                          __float2bfloat16(p3 - __bfloat162float(a3)));
            }
#pragma unroll
        for (int h2 = 0; h2 < 2; h2++) {
            float v = ls[h2];
            v += __shfl_xor_sync(0xffffffffu, v, 1);
            v += __shfl_xor_sync(0xffffffffu, v, 2);
            lsum[h2] = lsum[h2] * alpha[h2] + v;
        }
#pragma unroll
        for (int nto = 0; nto < 16; nto++)
#pragma unroll
            for (int e = 0; e < 4; e++) oacc[nto][e] *= alpha[e >> 1];

        // O += P @ V : 4 k16 steps over s, 16 n8 tiles over d, 3-term
#pragma unroll
        for (int ks2 = 0; ks2 < 4; ks2++) {
            const uint32_t kB = ks2 * 32;
#pragma unroll
            for (int ntp = 0; ntp < 8; ntp++) {
                uint32_t vh4[4], vl4[4];
                uint32_t boff = (uint32_t)(ntp * 16 + b4) * FV_S + kB + b_kB;
                ldsm_x4(vb + boff, vh4);
                ldsm_x4(vb + VPL + boff, vl4);
                mma_bf16(oacc[2 * ntp],     pfl[ks2], vh4);
                mma_bf16(oacc[2 * ntp],     pfh[ks2], vl4);
                mma_bf16(oacc[2 * ntp],     pfh[ks2], vh4);
                mma_bf16(oacc[2 * ntp + 1], pfl[ks2], vh4 + 2);
                mma_bf16(oacc[2 * ntp + 1], pfh[ks2], vl4 + 2);
                mma_bf16(oacc[2 * ntp + 1], pfh[ks2], vh4 + 2);
            }
        }
    }

    // epilogue: normalize, split, store hi/lo planes
    bf16* Ogh = Oh + (size_t)(b * SEQ + qt * 128) * (NH * HD) + h * HD;
    bf16* Ogl = Ol + (size_t)(b * SEQ + qt * 128) * (NH * HD) + h * HD;
#pragma unroll
    for (int h2 = 0; h2 < 2; h2++) {
        int r = wid * 16 + qrow + 8 * h2;
        float inv = 1.0f / lsum[h2];
#pragma unroll
        for (int nto = 0; nto < 16; nto++) {
            int c = nto * 8 + qcol;
            float v0 = oacc[nto][h2 * 2 + 0] * inv;
            float v1 = oacc[nto][h2 * 2 + 1] * inv;
            bf16 h0 = __float2bfloat16(v0), h1b = __float2bfloat16(v1);
            *(uint32_t*)(Ogh + (size_t)r * (NH * HD) + c) = pack2(h0, h1b);
            *(uint32_t*)(Ogl + (size_t)r * (NH * HD) + c) =
                pack2(__float2bfloat16(v0 - __bfloat162float(h0)),
                      __float2bfloat16(v1 - __bfloat162float(h1b)));
        }
    }
}

// ---------------- launch ----------------
extern "C" void kernel_launch(void* const* d_in, const int* in_sizes, int n_in,
                              void* d_out, int out_size) {
    const float* X  = (const float*)d_in[0];
    const float* cs = (const float*)d_in[1];
    const float* sn = (const float*)d_in[2];
    const float* Wq = (const float*)d_in[3];
    const float* Wk = (const float*)d_in[4];
    const float* Wv = (const float*)d_in[5];
    const float* Wo = (const float*)d_in[6];
    const float* qw = (const float*)d_in[7];
    const float* kw = (const float*)d_in[8];
    float* out = (float*)d_out;

    float* C;
    bf16 *Xh, *Xl, *Qh, *Ql, *Kh, *Kl, *Vth, *Vtl, *Oh, *Ol;
    bf16 *WcTh, *WcTl, *WoTh, *WoTl;
    cudaGetSymbolAddress((void**)&C,   g_C);
    cudaGetSymbolAddress((void**)&Xh,  g_Xh);  cudaGetSymbolAddress((void**)&Xl,  g_Xl);
    cudaGetSymbolAddress((void**)&Qh,  g_Qh);  cudaGetSymbolAddress((void**)&Ql,  g_Ql);
    cudaGetSymbolAddress((void**)&Kh,  g_Kh);  cudaGetSymbolAddress((void**)&Kl,  g_Kl);
    cudaGetSymbolAddress((void**)&Vth, g_Vth); cudaGetSymbolAddress((void**)&Vtl, g_Vtl);
    cudaGetSymbolAddress((void**)&Oh,  g_Oh);  cudaGetSymbolAddress((void**)&Ol,  g_Ol);
    cudaGetSymbolAddress((void**)&WcTh, g_WcTh); cudaGetSymbolAddress((void**)&WcTl, g_WcTl);
    cudaGetSymbolAddress((void**)&WoTh, g_WoTh); cudaGetSymbolAddress((void**)&WoTl, g_WoTl);

    cudaFuncSetAttribute(bf16x3_gemm_kernel, cudaFuncAttributeMaxDynamicSharedMemorySize,
                         GM_SMEM_BYTES);
    cudaFuncSetAttribute(flash_kernel, cudaFuncAttributeMaxDynamicSharedMemorySize,
                         FLASH_SMEM_BYTES);

    // operand preparation (weights concatenated into one [3072][2048] operand)
    split_kernel<<<(TOKENS * HID) / 1024, 256>>>(X, Xh, Xl);
    transpose_split_kernel<<<dim3(2048 / 32, 2048 / 32), dim3(32, 8)>>>(
        Wq, WcTh, WcTl, 2048, 2048);
    transpose_split_kernel<<<dim3(512 / 32, 2048 / 32), dim3(32, 8)>>>(
        Wk, WcTh + (size_t)2048 * 2048, WcTl + (size_t)2048 * 2048, 2048, 512);
    transpose_split_kernel<<<dim3(512 / 32, 2048 / 32), dim3(32, 8)>>>(
        Wv, WcTh + (size_t)2560 * 2048, WcTl + (size_t)2560 * 2048, 2048, 512);
    transpose_split_kernel<<<dim3(2048 / 32, 2048 / 32), dim3(32, 8)>>>(
        Wo, WoTh, WoTl, 2048, 2048);

    // fused QKV projection: C[tok][0:2048]=Q, [2048:2560]=K, [2560:3072]=V
    bf16x3_gemm_kernel<<<dim3(NC / 128, TOKENS / 128), 256, GM_SMEM_BYTES>>>(
        Xh, Xl, WcTh, WcTl, C, TOKENS, NC, HID);

    // RMSNorm + RoPE -> planes; V transpose + split
    rmsnorm_rope_kernel<<<dim3(TOKENS, NH),  HD>>>(C, 0,    Qh, Ql, qw, cs, sn, NH);
    rmsnorm_rope_kernel<<<dim3(TOKENS, NKV), HD>>>(C, 2048, Kh, Kl, kw, cs, sn, NKV);
    vtrans_kernel<<<dim3(SEQ / 32, HD / 32, BATCH * NKV), dim3(32, 8)>>>(C, Vth, Vtl);

    // causal GQA flash attention (register-P, double-buffered)
    flash_kernel<<<dim3(SEQ / 128, NH, BATCH), 256, FLASH_SMEM_BYTES>>>(
        Qh, Ql, Kh, Kl, Vth, Vtl, Oh, Ol);

    // output projection
    bf16x3_gemm_kernel<<<dim3(2048 / 128, TOKENS / 128), 256, GM_SMEM_BYTES>>>(
        Oh, Ol, WoTh, WoTl, out, TOKENS, 2048, HID);
}